// round 17
// baseline (speedup 1.0000x reference)
#include <cuda_runtime.h>
#include <cuda_fp16.h>
#include <math.h>
#include <stdint.h>

// Problem constants
#define BB      4
#define TT      2048
#define DM      1024
#define NH      16
#define DH      64
#define BT      (BB * TT)        // 8192 rows
#define NQKV    (3 * DM)         // 3072

// Scratch (alloc-free rule: __device__ globals)
__device__ __half g_qkv[(size_t)BT * NQKV];  // 50.3 MB (fp16)
__device__ __half g_ao [(size_t)BT * DM];    // 16.8 MB (fp16)
__device__ __half g_xh [(size_t)BT * DM];    // 16.8 MB (x in fp16)
__device__ __half g_wtq[(size_t)NQKV * DM];  //  6.3 MB (Wqkv^T fp16)
__device__ __half g_wto[(size_t)DM * DM];    //  2.1 MB (Wout^T fp16)

// ---------------------------------------------------------------------------
// Helpers
// ---------------------------------------------------------------------------
__device__ __forceinline__ uint32_t smem_u32(const void* p) {
    uint32_t a;
    asm("{ .reg .u64 t; cvta.to.shared.u64 t, %1; cvt.u32.u64 %0, t; }" : "=r"(a) : "l"(p));
    return a;
}

#define CP16(dst, src)  asm volatile("cp.async.cg.shared.global [%0], [%1], 16;" :: "r"(dst), "l"(src))
#define CP_COMMIT()     asm volatile("cp.async.commit_group;")
#define CP_WAIT(n)      asm volatile("cp.async.wait_group %0;" :: "n"(n))

#define MBAR_INIT(a, c) asm volatile("mbarrier.init.shared.b64 [%0], %1;" :: "r"(a), "r"(c) : "memory")
#define MBAR_ARRIVE(a)  asm volatile("mbarrier.arrive.shared::cta.b64 _, [%0];" :: "r"(a) : "memory")
#define CP_MBAR_ARR(a)  asm volatile("cp.async.mbarrier.arrive.noinc.shared::cta.b64 [%0];" :: "r"(a) : "memory")
#define MBAR_WAIT(a, ph) do { \
    uint32_t _m = (a), _p = (ph), _d; \
    asm volatile("{ .reg .pred p; mbarrier.try_wait.parity.acquire.cta.shared::cta.b64 p, [%1], %2; selp.b32 %0,1,0,p; }" \
        : "=r"(_d) : "r"(_m), "r"(_p) : "memory"); \
    if (!_d) { \
        asm volatile("{ .reg .pred P1;\nW%=:\nmbarrier.try_wait.parity.acquire.cta.shared::cta.b64 P1, [%0], %1, 0x989680;\n@P1 bra.uni D%=;\nbra.uni W%=;\nD%=:\n}" \
            :: "r"(_m), "r"(_p) : "memory"); \
    } } while (0)

// m16n8k16 fp16 mma, fp32 accumulate.
__device__ __forceinline__ void mma16h(float* d, const uint32_t* a, uint32_t b0, uint32_t b1) {
    asm volatile(
        "mma.sync.aligned.m16n8k16.row.col.f32.f16.f16.f32 "
        "{%0,%1,%2,%3}, {%4,%5,%6,%7}, {%8,%9}, {%0,%1,%2,%3};"
        : "+f"(d[0]), "+f"(d[1]), "+f"(d[2]), "+f"(d[3])
        : "r"(a[0]), "r"(a[1]), "r"(a[2]), "r"(a[3]), "r"(b0), "r"(b1));
}

__device__ __forceinline__ void ldsm_x4(uint32_t& r0, uint32_t& r1, uint32_t& r2, uint32_t& r3,
                                        uint32_t addr) {
    asm volatile("ldmatrix.sync.aligned.m8n8.x4.shared.b16 {%0,%1,%2,%3}, [%4];"
        : "=r"(r0), "=r"(r1), "=r"(r2), "=r"(r3) : "r"(addr));
}
__device__ __forceinline__ void ldsm_x4_t(uint32_t& r0, uint32_t& r1, uint32_t& r2, uint32_t& r3,
                                          uint32_t addr) {
    asm volatile("ldmatrix.sync.aligned.m8n8.x4.trans.shared.b16 {%0,%1,%2,%3}, [%4];"
        : "=r"(r0), "=r"(r1), "=r"(r2), "=r"(r3) : "r"(addr));
}

// ---------------------------------------------------------------------------
// fp16 tensor-core GEMM (93% of mma.sync issue floor — unchanged from R13)
// ---------------------------------------------------------------------------
#define GPAD  40
#define GASZ  (128 * GPAD * 2)
#define GSTG  (2 * GASZ)
#define G_SMEM (3 * GSTG)

__global__ __launch_bounds__(256, 2) void gemm_h(
    const __half* __restrict__ A, const __half* __restrict__ Bt,
    float* __restrict__ Cf, __half* __restrict__ Ch,
    int M, int N, int K)
{
    extern __shared__ char smem_g[];
    const uint32_t sbase = smem_u32(smem_g);

    const int tid  = threadIdx.x;
    const int lane = tid & 31;
    const int wid  = tid >> 5;
    const int wm   = (wid >> 1) * 32;
    const int wn   = (wid & 1) * 64;
    const int g    = lane >> 2;
    const int tg   = lane & 3;

    const int bx = blockIdx.x, by = blockIdx.y;

    const int lrow = tid >> 1;
    const int colb = (tid & 1) * 16;
    const uint32_t dOff = (uint32_t)(lrow * GPAD + colb) * 2;
    const __half* gA = A  + (size_t)(by * 128) * K;
    const __half* gB = Bt + (size_t)(bx * 128) * K;

    const int mi = lane >> 3, lr = lane & 7;
    const int aRow = lr + ((mi & 1) << 3);
    const int aCol = (mi & 2) << 2;
    const int bRow = lr + ((mi >> 1) << 3);
    const int bCol = (mi & 1) << 3;

    float acc[2][8][4];
    #pragma unroll
    for (int i = 0; i < 2; i++)
        #pragma unroll
        for (int j = 0; j < 8; j++)
            #pragma unroll
            for (int q = 0; q < 4; q++) acc[i][j][q] = 0.f;

    const int NC = K / 32;

    {
        const uint32_t dA0 = sbase + dOff;
        CP16(dA0,              gA + (size_t)lrow * K + colb);
        CP16(dA0 + 16,         gA + (size_t)lrow * K + colb + 8);
        CP16(dA0 + GASZ,       gB + (size_t)lrow * K + colb);
        CP16(dA0 + GASZ + 16,  gB + (size_t)lrow * K + colb + 8);
        CP_COMMIT();
        const uint32_t dA1 = sbase + GSTG + dOff;
        CP16(dA1,              gA + (size_t)lrow * K + 32 + colb);
        CP16(dA1 + 16,         gA + (size_t)lrow * K + 32 + colb + 8);
        CP16(dA1 + GASZ,       gB + (size_t)lrow * K + 32 + colb);
        CP16(dA1 + GASZ + 16,  gB + (size_t)lrow * K + 32 + colb + 8);
        CP_COMMIT();
    }

    for (int c = 0; c < NC; c++) {
        CP_WAIT(1);
        __syncthreads();
        if (c + 2 < NC) {
            const int k0 = (c + 2) * 32;
            const uint32_t dA = sbase + (uint32_t)((c + 2) % 3) * GSTG + dOff;
            CP16(dA,             gA + (size_t)lrow * K + k0 + colb);
            CP16(dA + 16,        gA + (size_t)lrow * K + k0 + colb + 8);
            CP16(dA + GASZ,      gB + (size_t)lrow * K + k0 + colb);
            CP16(dA + GASZ + 16, gB + (size_t)lrow * K + k0 + colb + 8);
        }
        CP_COMMIT();

        const uint32_t aoff = sbase + (uint32_t)(c % 3) * GSTG;
        const uint32_t boff = aoff + GASZ;
        #pragma unroll
        for (int ks = 0; ks < 2; ks++) {
            uint32_t a0[4], a1[4];
            ldsm_x4(a0[0], a0[1], a0[2], a0[3],
                    aoff + (uint32_t)((wm + aRow) * GPAD + ks * 16 + aCol) * 2);
            ldsm_x4(a1[0], a1[1], a1[2], a1[3],
                    aoff + (uint32_t)((wm + 16 + aRow) * GPAD + ks * 16 + aCol) * 2);
            uint32_t bb[8][2];
            #pragma unroll
            for (int ntp = 0; ntp < 4; ntp++) {
                uint32_t r0, r1, r2, r3;
                ldsm_x4(r0, r1, r2, r3,
                        boff + (uint32_t)((wn + ntp * 16 + bRow) * GPAD + ks * 16 + bCol) * 2);
                bb[2 * ntp][0] = r0; bb[2 * ntp][1] = r1;
                bb[2 * ntp + 1][0] = r2; bb[2 * ntp + 1][1] = r3;
            }
            #pragma unroll
            for (int nt = 0; nt < 8; nt++) {
                mma16h(acc[0][nt], a0, bb[nt][0], bb[nt][1]);
                mma16h(acc[1][nt], a1, bb[nt][0], bb[nt][1]);
            }
        }
    }

    #pragma unroll
    for (int mt = 0; mt < 2; mt++) {
        const size_t r0 = (size_t)(by * 128 + wm + mt * 16 + g);
        #pragma unroll
        for (int nt = 0; nt < 8; nt++) {
            const int col = bx * 128 + wn + nt * 8 + 2 * tg;
            if (Ch) {
                *(__half2*)(Ch + r0 * N + col) =
                    __floats2half2_rn(acc[mt][nt][0], acc[mt][nt][1]);
                *(__half2*)(Ch + (r0 + 8) * N + col) =
                    __floats2half2_rn(acc[mt][nt][2], acc[mt][nt][3]);
            } else {
                *(float2*)(Cf + r0 * N + col)       = make_float2(acc[mt][nt][0], acc[mt][nt][1]);
                *(float2*)(Cf + (r0 + 8) * N + col) = make_float2(acc[mt][nt][2], acc[mt][nt][3]);
            }
        }
    }
}

// ---------------------------------------------------------------------------
// Fused prologue: one launch does x->fp16 convert + both weight transposes.
// Blocks [0,8192): convert; [8192,11264): Wqkv^T; [11264,12288): Wout^T.
// ---------------------------------------------------------------------------
#define PRO_BLOCKS 12288
__global__ __launch_bounds__(256) void prologue_fused(
    const float* __restrict__ x, const float* __restrict__ Wqkv,
    const float* __restrict__ Wout,
    __half* __restrict__ xh, __half* __restrict__ wtq, __half* __restrict__ wto)
{
    __shared__ float t[32][33];
    const int blk = blockIdx.x;
    if (blk < 8192) {
        int i = blk * 256 + threadIdx.x;
        float4 v = ((const float4*)x)[i];
        __half2* o = (__half2*)xh;
        o[2 * i]     = __floats2half2_rn(v.x, v.y);
        o[2 * i + 1] = __floats2half2_rn(v.z, v.w);
    } else {
        const float* in;
        __half* out;
        int cols, bi;
        if (blk < 8192 + 3072) { bi = blk - 8192;  in = Wqkv; out = wtq; cols = NQKV; }
        else                   { bi = blk - 11264; in = Wout; out = wto; cols = DM;   }
        const int rows = DM;
        const int nbx = cols / 32;
        const int bx = (bi % nbx) * 32;
        const int by = (bi / nbx) * 32;
        const int tx = threadIdx.x & 31;
        const int ty = threadIdx.x >> 5;
        #pragma unroll
        for (int i2 = ty; i2 < 32; i2 += 8)
            t[i2][tx] = in[(size_t)(by + i2) * cols + bx + tx];
        __syncthreads();
        #pragma unroll
        for (int i2 = ty; i2 < 32; i2 += 8)
            out[(size_t)(bx + i2) * rows + by + tx] = __float2half_rn(t[tx][i2]);
    }
}

// ---------------------------------------------------------------------------
// fp16 flash attention (causal), mbarrier producer/consumer pipeline.
// grid: (T/128, B*NH), block 256 (8 warps), warp = 16 query rows.
// R17: ALL warps produce every K/V tile (4 CP16/thread; full count=256),
// l summed in fp32 pre-rounding, register P fragments (R16).
// ---------------------------------------------------------------------------
#define PADH 72
#define FA_S 4
#define FA_KSTG (64 * PADH * 2)                 // 9216 B per K (or V) stage
#define OFF_K   128
#define OFF_V   (OFF_K + FA_S * FA_KSTG)        // 36992
#define FA_SMEM (OFF_V + FA_S * FA_KSTG)        // 73856 B

__global__ __launch_bounds__(256, 2) void flash_attn_h(
    const __half* __restrict__ qkv, __half* __restrict__ ao)
{
    extern __shared__ char smf[];
    const uint32_t sb   = smem_u32(smf);
    const uint32_t ksb  = sb + OFF_K;
    const uint32_t vsb  = sb + OFF_V;
    const uint32_t mbF  = sb;          // full[0..3]  at +0,8,16,24
    const uint32_t mbE  = sb + 32;     // empty[0..3] at +32..56

    const int qb2  = (gridDim.x - 1) - blockIdx.x;  // heavy blocks first
    const int bh   = blockIdx.y;
    const int b    = bh >> 4;
    const int h    = bh & 15;
    const int tid  = threadIdx.x;
    const int lane = tid & 31;
    const int wid  = tid >> 5;
    const int g    = lane >> 2;
    const int tg   = lane & 3;
    const int r0   = wid * 16;
    const int qRowBase = qb2 * 128 + r0;
    const size_t rowbase = (size_t)(b * TT);
    const int lastT = 2 * qb2 + 1;

    // ldmatrix B-fragment per-lane offsets (K tiles)
    const int mi = lane >> 3, lr = lane & 7;
    const int bRow = lr + ((mi >> 1) << 3);
    const int bCol = (mi & 1) << 3;

    if (tid == 0) {
        #pragma unroll
        for (int s = 0; s < FA_S; s++) {
            MBAR_INIT(mbF + 8 * s, 256);
            MBAR_INIT(mbE + 8 * s, 8);
        }
    }
    __syncthreads();

    // K/V source base for this (b,h)
    const __half* kvsrc = qkv + rowbase * NQKV + DM + h * DH;

    // per-thread produce map: 4 CP16/tile; f in [0,1024): kv = f>>9,
    // f5 = f&511 -> row = f5>>3, col = (f5&7)*8
    // prologue: all warps produce tiles 0..min(FA_S-1, lastT)
    #pragma unroll
    for (int pt = 0; pt < FA_S; pt++) {
        if (pt <= lastT) {
            const __half* src = kvsrc + (size_t)(pt * 64) * NQKV;
            const uint32_t kd = ksb + (uint32_t)pt * FA_KSTG;
            const uint32_t vd = vsb + (uint32_t)pt * FA_KSTG;
            #pragma unroll
            for (int i = 0; i < 4; i++) {
                int f  = tid + i * 256;
                int kv = f >> 9;
                int f5 = f & 511;
                int row = f5 >> 3;
                int col = (f5 & 7) * 8;
                uint32_t dst = (kv ? vd : kd) + (uint32_t)(row * PADH + col) * 2;
                CP16(dst, src + (size_t)row * NQKV + kv * DM + col);
            }
            CP_MBAR_ARR(mbF + 8 * pt);
        }
    }

    // Q fragments (x 0.125, exact in fp16)
    uint32_t qa[4][4];
    {
        const __half* qp = qkv + (rowbase + (size_t)qRowBase) * NQKV + h * DH;
        const __half2 sc = __floats2half2_rn(0.125f, 0.125f);
        #pragma unroll
        for (int kc = 0; kc < 4; kc++) {
            #pragma unroll
            for (int e = 0; e < 4; e++) {
                int dr = (e & 1) * 8;
                int dc = (e >> 1) * 8;
                __half2 v = *(const __half2*)(qp + (size_t)(g + dr) * NQKV + kc * 16 + dc + 2 * tg);
                v = __hmul2(v, sc);
                qa[kc][e] = *(const uint32_t*)&v;
            }
        }
    }

    float O[8][4];
    #pragma unroll
    for (int nc = 0; nc < 8; nc++)
        #pragma unroll
        for (int e = 0; e < 4; e++) O[nc][e] = 0.f;
    float m0 = -1e30f, m1 = -1e30f, l0 = 0.f, l1 = 0.f;

    // V ldmatrix.x4.trans per-lane address component
    const uint32_t vLaneOff = (uint32_t)((lane & 15) * PADH + ((lane >> 4) & 1) * 8) * 2;

    for (int kb = 0; kb <= lastT; kb++) {
        const int s = kb & (FA_S - 1);

        // all warps: refill stage with tile kb+FA_S-1
        if (kb >= 1) {
            const int pt = kb + FA_S - 1;
            if (pt <= lastT) {
                const int ps = pt & (FA_S - 1);
                MBAR_WAIT(mbE + 8 * ps, (uint32_t)(((pt >> 2) - 1) & 1));
                const __half* src = kvsrc + (size_t)(pt * 64) * NQKV;
                const uint32_t kd = ksb + (uint32_t)ps * FA_KSTG;
                const uint32_t vd = vsb + (uint32_t)ps * FA_KSTG;
                #pragma unroll
                for (int i = 0; i < 4; i++) {
                    int f  = tid + i * 256;
                    int kv = f >> 9;
                    int f5 = f & 511;
                    int row = f5 >> 3;
                    int col = (f5 & 7) * 8;
                    uint32_t dst = (kv ? vd : kd) + (uint32_t)(row * PADH + col) * 2;
                    CP16(dst, src + (size_t)row * NQKV + kv * DM + col);
                }
                CP_MBAR_ARR(mbF + 8 * ps);
            }
        }

        // consume tile kb
        MBAR_WAIT(mbF + 8 * s, (uint32_t)((kb >> 2) & 1));

        const int iloc = qRowBase - kb * 64;
        if (iloc > -16) {
            const uint32_t ksAddr = ksb + (uint32_t)s * FA_KSTG;
            const uint32_t vAddr  = vsb + (uint32_t)s * FA_KSTG + vLaneOff;

            // number of active 16-key chunks (warp-uniform)
            int ntpMax = ((iloc + 15) >> 4) + 1;
            if (ntpMax > 4) ntpMax = 4;

            // ---- S = (Q*scale) K^T ----
            float Sc[8][4];
            #pragma unroll
            for (int nc = 0; nc < 8; nc++)
                #pragma unroll
                for (int e = 0; e < 4; e++) Sc[nc][e] = 0.f;

            #pragma unroll
            for (int kc = 0; kc < 4; kc++) {
                #pragma unroll
                for (int ntp = 0; ntp < 4; ntp++) {
                    if (ntp < ntpMax) {
                        uint32_t b0, b1, b2, b3;
                        ldsm_x4(b0, b1, b2, b3,
                                ksAddr + (uint32_t)((ntp * 16 + bRow) * PADH + kc * 16 + bCol) * 2);
                        mma16h(Sc[2 * ntp],     qa[kc], b0, b1);
                        mma16h(Sc[2 * ntp + 1], qa[kc], b2, b3);
                    }
                }
            }

            // ---- causal mask (diagonal-overlapping tiles) ----
            if (iloc < 63) {
                const int i0 = iloc + g, i1 = iloc + g + 8;
                #pragma unroll
                for (int nc = 0; nc < 8; nc++) {
                    int j = nc * 8 + 2 * tg;
                    if (j     > i0) Sc[nc][0] = -1e30f;
                    if (j + 1 > i0) Sc[nc][1] = -1e30f;
                    if (j     > i1) Sc[nc][2] = -1e30f;
                    if (j + 1 > i1) Sc[nc][3] = -1e30f;
                }
            }

            // ---- online softmax ----
            float rx0 = -1e30f, rx1 = -1e30f;
            #pragma unroll
            for (int nc = 0; nc < 8; nc++) {
                rx0 = fmaxf(rx0, fmaxf(Sc[nc][0], Sc[nc][1]));
                rx1 = fmaxf(rx1, fmaxf(Sc[nc][2], Sc[nc][3]));
            }
            rx0 = fmaxf(rx0, __shfl_xor_sync(0xFFFFFFFF, rx0, 1));
            rx0 = fmaxf(rx0, __shfl_xor_sync(0xFFFFFFFF, rx0, 2));
            rx1 = fmaxf(rx1, __shfl_xor_sync(0xFFFFFFFF, rx1, 1));
            rx1 = fmaxf(rx1, __shfl_xor_sync(0xFFFFFFFF, rx1, 2));

            const float mn0 = fmaxf(m0, rx0);
            const float mn1 = fmaxf(m1, rx1);
            const float a0 = __expf(m0 - mn0);
            const float a1 = __expf(m1 - mn1);
            m0 = mn0; m1 = mn1;

            // exp -> fp16 P kept in registers; l summed in fp32 (pre-rounding)
            uint32_t p01[8], p23[8];
            float s0 = 0.f, s1 = 0.f;
            #pragma unroll
            for (int nc = 0; nc < 8; nc++) {
                float e0 = __expf(Sc[nc][0] - mn0);
                float e1 = __expf(Sc[nc][1] - mn0);
                float e2 = __expf(Sc[nc][2] - mn1);
                float e3 = __expf(Sc[nc][3] - mn1);
                s0 += e0 + e1;
                s1 += e2 + e3;
                __half2 h01 = __floats2half2_rn(e0, e1);
                __half2 h23 = __floats2half2_rn(e2, e3);
                p01[nc] = *(const uint32_t*)&h01;
                p23[nc] = *(const uint32_t*)&h23;
            }
            l0 = l0 * a0 + s0;
            l1 = l1 * a1 + s1;

            // skip O-rescale when max unchanged (x1.0 is an fp32 identity)
            if (!__all_sync(0xFFFFFFFF, (a0 == 1.f) && (a1 == 1.f))) {
                #pragma unroll
                for (int nc = 0; nc < 8; nc++) {
                    O[nc][0] *= a0; O[nc][1] *= a0;
                    O[nc][2] *= a1; O[nc][3] *= a1;
                }
            }

            // ---- O += P V : P frags from registers, V via ldmatrix.x4.trans ----
            #pragma unroll
            for (int kc = 0; kc < 4; kc++) {
                if (kc < ntpMax) {
                    uint32_t pa[4];
                    pa[0] = p01[2 * kc];
                    pa[1] = p23[2 * kc];
                    pa[2] = p01[2 * kc + 1];
                    pa[3] = p23[2 * kc + 1];
                    #pragma unroll
                    for (int ncp = 0; ncp < 4; ncp++) {
                        uint32_t b0, b1, b2, b3;
                        ldsm_x4_t(b0, b1, b2, b3,
                                  vAddr + (uint32_t)(kc * 16 * PADH + ncp * 16) * 2);
                        mma16h(O[2 * ncp],     pa, b0, b1);
                        mma16h(O[2 * ncp + 1], pa, b2, b3);
                    }
                }
            }
        }

        // every warp releases the stage (even if it skipped compute)
        if (lane == 0) MBAR_ARRIVE(mbE + 8 * s);
    }

    // ---- final l reduction, normalize, write fp16 ao ----
    l0 += __shfl_xor_sync(0xFFFFFFFF, l0, 1);
    l0 += __shfl_xor_sync(0xFFFFFFFF, l0, 2);
    l1 += __shfl_xor_sync(0xFFFFFFFF, l1, 1);
    l1 += __shfl_xor_sync(0xFFFFFFFF, l1, 2);
    const float inv0 = 1.f / l0;
    const float inv1 = 1.f / l1;
    __half* op0 = ao + (rowbase + (size_t)(qRowBase + g))     * DM + h * DH;
    __half* op1 = ao + (rowbase + (size_t)(qRowBase + g + 8)) * DM + h * DH;
    #pragma unroll
    for (int nc = 0; nc < 8; nc++) {
        *(__half2*)(op0 + nc * 8 + 2 * tg) =
            __floats2half2_rn(O[nc][0] * inv0, O[nc][1] * inv0);
        *(__half2*)(op1 + nc * 8 + 2 * tg) =
            __floats2half2_rn(O[nc][2] * inv1, O[nc][3] * inv1);
    }
}

// ---------------------------------------------------------------------------
extern "C" void kernel_launch(void* const* d_in, const int* in_sizes, int n_in,
                              void* d_out, int out_size)
{
    const float* x    = (const float*)d_in[0];   // [B,T,1024]
    const float* Wqkv = (const float*)d_in[1];   // [1024,3072]
    const float* Wout = (const float*)d_in[2];   // [1024,1024]
    float* out = (float*)d_out;

    __half *qkv, *ao, *xh, *wtq, *wto;
    cudaGetSymbolAddress((void**)&qkv, g_qkv);
    cudaGetSymbolAddress((void**)&ao,  g_ao);
    cudaGetSymbolAddress((void**)&xh,  g_xh);
    cudaGetSymbolAddress((void**)&wtq, g_wtq);
    cudaGetSymbolAddress((void**)&wto, g_wto);

    cudaFuncSetAttribute(gemm_h, cudaFuncAttributeMaxDynamicSharedMemorySize, G_SMEM);
    cudaFuncSetAttribute(flash_attn_h, cudaFuncAttributeMaxDynamicSharedMemorySize, FA_SMEM);

    // Fused prologue: x -> fp16 + both weight transposes in ONE launch
    prologue_fused<<<PRO_BLOCKS, 256>>>(x, Wqkv, Wout, xh, wtq, wto);

    // 1) QKV projection (fp16 mma, fp16 output)
    gemm_h<<<dim3(NQKV / 128, BT / 128), 256, G_SMEM>>>(xh, wtq, nullptr, qkv, BT, NQKV, DM);

    // 2) Causal flash attention (mbarrier-pipelined, symmetric producers)
    flash_attn_h<<<dim3(TT / 128, BB * NH), 256, FA_SMEM>>>(qkv, ao);

    // 3) Output projection (fp16 mma, fp32 output)
    gemm_h<<<dim3(DM / 128, BT / 128), 256, G_SMEM>>>(ao, wto, out, nullptr, BT, DM, DM);
}